// round 10
// baseline (speedup 1.0000x reference)
#include <cuda_runtime.h>

#define NN    100000
#define EDGES 3200000
#define INC   128
#define HID   16
#define OUTC  64

// Scratch (allocation-free rule: __device__ globals)
__device__ __align__(16) int   g_deg_i[NN];
__device__ __align__(16) float g_dinv[NN];
__device__ __align__(16) int   g_off[NN + 1];
__device__ __align__(16) int   g_cur[NN];
__device__ __align__(16) int   g_src[EDGES];
__device__ __align__(16) float g_h[NN * HID];    // h1, then relu(h)
__device__ __align__(16) float g_agg[NN * HID];  // agg1, then agg2

__global__ void k_init_deg() {
    int i = blockIdx.x * blockDim.x + threadIdx.x;
    if (i < NN) g_deg_i[i] = 1;  // self loop contributes 1
}

__global__ void k_count(const int* __restrict__ col, int E) {
    int e = blockIdx.x * blockDim.x + threadIdx.x;
    if (e < E) atomicAdd(&g_deg_i[col[e]], 1);
}

__global__ void k_dinv() {
    int i = blockIdx.x * blockDim.x + threadIdx.x;
    if (i < NN) g_dinv[i] = rsqrtf((float)g_deg_i[i]);
}

// Single-block exclusive scan of in-degrees (deg-1) -> g_off, g_cur. 1024 threads.
__global__ void k_scan() {
    __shared__ int part[1024];
    const int chunk = (NN + 1023) / 1024;  // 98
    int t = threadIdx.x;
    int start = t * chunk;
    int end = start + chunk; if (end > NN) end = NN;
    int s = 0;
    for (int i = start; i < end; i++) s += g_deg_i[i] - 1;
    part[t] = s;
    __syncthreads();
    for (int off = 1; off < 1024; off <<= 1) {
        int v = (t >= off) ? part[t - off] : 0;
        __syncthreads();
        part[t] += v;
        __syncthreads();
    }
    int run = (t == 0) ? 0 : part[t - 1];
    for (int i = start; i < end; i++) {
        g_off[i] = run;
        g_cur[i] = run;
        run += g_deg_i[i] - 1;
    }
    if (t == 1023) g_off[NN] = run;  // == E
}

__global__ void k_scatter(const int* __restrict__ row,
                          const int* __restrict__ col, int E) {
    int e = blockIdx.x * blockDim.x + threadIdx.x;
    if (e >= E) return;
    int p = atomicAdd(&g_cur[col[e]], 1);
    g_src[p] = row[e];
}

// h = X @ W1. Vectorized: 2x LDS.128 + 4 FFMA per 4 k's. 16 rows / 256-thread block.
__global__ void k_gemm1(const float* __restrict__ x, const float* __restrict__ W1) {
    __shared__ float4 xs[16 * 32];    // 16 rows x 32 float4 (K=128)
    __shared__ float4 wsT[16 * 33];   // 16 cols x 32 float4, stride 33 (pad)
    int r0 = blockIdx.x * 16;
    int t = threadIdx.x;
    const float4* xg = (const float4*)x;
    for (int i = t; i < 512; i += 256)
        xs[i] = xg[r0 * 32 + i];
    for (int i = t; i < 512; i += 256) {
        int c = i >> 5, k4 = i & 31;
        float4 w;
        w.x = W1[(k4 * 4 + 0) * 16 + c];
        w.y = W1[(k4 * 4 + 1) * 16 + c];
        w.z = W1[(k4 * 4 + 2) * 16 + c];
        w.w = W1[(k4 * 4 + 3) * 16 + c];
        wsT[c * 33 + k4] = w;
    }
    __syncthreads();
    int r = t >> 4, c = t & 15;
    float acc = 0.0f;
#pragma unroll
    for (int k4 = 0; k4 < 32; k4++) {
        float4 xv = xs[r * 32 + k4];
        float4 wv = wsT[c * 33 + k4];
        acc = fmaf(xv.x, wv.x, acc);
        acc = fmaf(xv.y, wv.y, acc);
        acc = fmaf(xv.z, wv.z, acc);
        acc = fmaf(xv.w, wv.w, acc);
    }
    g_h[(r0 + r) * HID + c] = acc;
}

// Pull-mode aggregation: g_agg = Ahat-aggregate of g_h.
// 4 threads per node, thread j owns cols [4j, 4j+4). Globals referenced from
// device code (host code must NOT pass __device__ symbols as arguments).
__global__ void k_pull() {
    unsigned gid = blockIdx.x * blockDim.x + threadIdx.x;
    int n = gid >> 2;
    int j = gid & 3;
    if (n >= NN) return;
    float din = g_dinv[n];
    const float4* H = (const float4*)g_h;
    float4 acc = H[n * 4 + j];
    float w0 = din * din;
    acc.x *= w0; acc.y *= w0; acc.z *= w0; acc.w *= w0;
    int e = g_off[n], eend = g_off[n + 1];
    for (; e + 1 < eend; e += 2) {
        int s0 = g_src[e], s1 = g_src[e + 1];
        float wa = g_dinv[s0] * din, wb = g_dinv[s1] * din;
        float4 v0 = H[s0 * 4 + j], v1 = H[s1 * 4 + j];
        acc.x += v0.x * wa + v1.x * wb;
        acc.y += v0.y * wa + v1.y * wb;
        acc.z += v0.z * wa + v1.z * wb;
        acc.w += v0.w * wa + v1.w * wb;
    }
    if (e < eend) {
        int s = g_src[e];
        float wa = g_dinv[s] * din;
        float4 v = H[s * 4 + j];
        acc.x += v.x * wa; acc.y += v.y * wa; acc.z += v.z * wa; acc.w += v.w * wa;
    }
    ((float4*)g_agg)[n * 4 + j] = acc;
}

// g_h = relu(g_agg + b1), float4-wide.
__global__ void k_relu(const float* __restrict__ b1) {
    int q = blockIdx.x * blockDim.x + threadIdx.x;  // quad index
    if (q >= NN * 4) return;
    float4 b = ((const float4*)b1)[q & 3];
    float4 v = ((const float4*)g_agg)[q];
    v.x = fmaxf(v.x + b.x, 0.0f);
    v.y = fmaxf(v.y + b.y, 0.0f);
    v.z = fmaxf(v.z + b.z, 0.0f);
    v.w = fmaxf(v.w + b.w, 0.0f);
    ((float4*)g_h)[q] = v;
}

// out = g_agg @ W2 + b2. 4 rows per 256-thread block.
__global__ void k_gemm2(const float* __restrict__ W2, const float* __restrict__ b2,
                        float* __restrict__ out) {
    __shared__ float as[4 * 16];
    __shared__ float ws[16 * 64];
    int r0 = blockIdx.x * 4;
    int t = threadIdx.x;
    if (t < 64) as[t] = g_agg[r0 * HID + t];
    for (int i = t; i < 16 * 64; i += 256) ws[i] = W2[i];
    __syncthreads();
    int r = t >> 6, c = t & 63;
    float acc = b2[c];
#pragma unroll
    for (int k = 0; k < 16; k++)
        acc = fmaf(as[r * 16 + k], ws[k * 64 + c], acc);
    out[(r0 + r) * OUTC + c] = acc;
}

extern "C" void kernel_launch(void* const* d_in, const int* in_sizes, int n_in,
                              void* d_out, int out_size) {
    const float* x   = (const float*)d_in[0];
    const int*   ei  = (const int*)d_in[1];   // JAX silently downcast int64->int32
    const float* W1  = (const float*)d_in[2];
    const float* b1  = (const float*)d_in[3];
    const float* W2  = (const float*)d_in[4];
    const float* b2  = (const float*)d_in[5];
    float*       out = (float*)d_out;

    int E = in_sizes[1] / 2;
    const int* row = ei;       // sources
    const int* col = ei + E;   // targets

    k_init_deg<<<(NN + 255) / 256, 256>>>();
    k_count<<<(E + 255) / 256, 256>>>(col, E);
    k_dinv<<<(NN + 255) / 256, 256>>>();
    k_scan<<<1, 1024>>>();
    k_scatter<<<(E + 255) / 256, 256>>>(row, col, E);
    k_gemm1<<<NN / 16, 256>>>(x, W1);
    k_pull<<<(NN * 4 + 255) / 256, 256>>>();
    k_relu<<<(NN * 4 + 255) / 256, 256>>>(b1);
    k_pull<<<(NN * 4 + 255) / 256, 256>>>();
    k_gemm2<<<NN / 4, 256>>>(W2, b2, out);
}

// round 11
// speedup vs baseline: 1.5689x; 1.5689x over previous
#include <cuda_runtime.h>

#define NN    100000
#define EDGES 3200000
#define INC   128
#define HID   16
#define OUTC  64
#define NBLK  ((NN + 1023) / 1024)   // 98

// Scratch (allocation-free rule: __device__ globals)
__device__ __align__(16) int   g_deg_i[NN];
__device__ __align__(16) float g_dinv[NN];
__device__ __align__(16) int   g_off[NN + 1];
__device__ __align__(16) int   g_cur[NN];
__device__ __align__(16) int   g_src[EDGES];
__device__ __align__(16) int   g_bsum[NBLK];
__device__ __align__(16) int   g_boff[NBLK];
__device__ __align__(16) float g_h[NN * HID];    // h1, then relu(h)
__device__ __align__(16) float g_agg[NN * HID];  // agg1, then agg2

__global__ void k_init_deg() {
    int i = blockIdx.x * blockDim.x + threadIdx.x;
    if (i < NN) g_deg_i[i] = 1;  // self loop contributes 1
}

__global__ void k_count(const int* __restrict__ col, int E) {
    int e = blockIdx.x * blockDim.x + threadIdx.x;
    if (e < E) atomicAdd(&g_deg_i[col[e]], 1);
}

__global__ void k_dinv() {
    int i = blockIdx.x * blockDim.x + threadIdx.x;
    if (i < NN) g_dinv[i] = rsqrtf((float)g_deg_i[i]);
}

// ---- 3-phase multi-block exclusive scan of (deg-1) -> g_off, g_cur ----
__global__ void k_blocksum() {
    __shared__ int sh[1024];
    int t = threadIdx.x;
    int i = blockIdx.x * 1024 + t;
    sh[t] = (i < NN) ? g_deg_i[i] - 1 : 0;
    __syncthreads();
    for (int o = 512; o > 0; o >>= 1) {
        if (t < o) sh[t] += sh[t + o];
        __syncthreads();
    }
    if (t == 0) g_bsum[blockIdx.x] = sh[0];
}

__global__ void k_bscan() {  // 1 block, 128 threads >= NBLK
    __shared__ int sh[128];
    int t = threadIdx.x;
    int v = (t < NBLK) ? g_bsum[t] : 0;
    sh[t] = v;
    __syncthreads();
    for (int o = 1; o < 128; o <<= 1) {
        int u = (t >= o) ? sh[t - o] : 0;
        __syncthreads();
        sh[t] += u;
        __syncthreads();
    }
    if (t < NBLK) g_boff[t] = sh[t] - v;  // exclusive
}

__global__ void k_off() {
    __shared__ int sh[1024];
    int t = threadIdx.x;
    int i = blockIdx.x * 1024 + t;
    int v = (i < NN) ? g_deg_i[i] - 1 : 0;
    sh[t] = v;
    __syncthreads();
    for (int o = 1; o < 1024; o <<= 1) {  // inclusive Hillis-Steele
        int u = (t >= o) ? sh[t - o] : 0;
        __syncthreads();
        sh[t] += u;
        __syncthreads();
    }
    int excl = sh[t] - v + g_boff[blockIdx.x];
    if (i < NN) {
        g_off[i] = excl;
        g_cur[i] = excl;
        if (i == NN - 1) g_off[NN] = excl + v;
    }
}

__global__ void k_scatter(const int* __restrict__ row,
                          const int* __restrict__ col, int E) {
    int e = blockIdx.x * blockDim.x + threadIdx.x;
    if (e >= E) return;
    int p = atomicAdd(&g_cur[col[e]], 1);
    g_src[p] = row[e];
}

// h = X @ W1. Vectorized: 2x LDS.128 + 4 FFMA per 4 k's. 16 rows / 256-thread block.
__global__ void k_gemm1(const float* __restrict__ x, const float* __restrict__ W1) {
    __shared__ float4 xs[16 * 32];    // 16 rows x 32 float4 (K=128)
    __shared__ float4 wsT[16 * 33];   // 16 cols x 32 float4, stride 33 (pad)
    int r0 = blockIdx.x * 16;
    int t = threadIdx.x;
    const float4* xg = (const float4*)x;
    for (int i = t; i < 512; i += 256)
        xs[i] = xg[r0 * 32 + i];
    for (int i = t; i < 512; i += 256) {
        int c = i >> 5, k4 = i & 31;
        float4 w;
        w.x = W1[(k4 * 4 + 0) * 16 + c];
        w.y = W1[(k4 * 4 + 1) * 16 + c];
        w.z = W1[(k4 * 4 + 2) * 16 + c];
        w.w = W1[(k4 * 4 + 3) * 16 + c];
        wsT[c * 33 + k4] = w;
    }
    __syncthreads();
    int r = t >> 4, c = t & 15;
    float acc = 0.0f;
#pragma unroll
    for (int k4 = 0; k4 < 32; k4++) {
        float4 xv = xs[r * 32 + k4];
        float4 wv = wsT[c * 33 + k4];
        acc = fmaf(xv.x, wv.x, acc);
        acc = fmaf(xv.y, wv.y, acc);
        acc = fmaf(xv.z, wv.z, acc);
        acc = fmaf(xv.w, wv.w, acc);
    }
    g_h[(r0 + r) * HID + c] = acc;
}

// Pull-mode aggregation: g_agg = Ahat-aggregate of g_h.
// 4 threads per node, thread j owns cols [4j, 4j+4).
__global__ void k_pull() {
    unsigned gid = blockIdx.x * blockDim.x + threadIdx.x;
    int n = gid >> 2;
    int j = gid & 3;
    if (n >= NN) return;
    float din = g_dinv[n];
    const float4* H = (const float4*)g_h;
    float4 acc = H[n * 4 + j];
    float w0 = din * din;
    acc.x *= w0; acc.y *= w0; acc.z *= w0; acc.w *= w0;
    int e = g_off[n], eend = g_off[n + 1];
    for (; e + 1 < eend; e += 2) {
        int s0 = g_src[e], s1 = g_src[e + 1];
        float wa = g_dinv[s0] * din, wb = g_dinv[s1] * din;
        float4 v0 = H[s0 * 4 + j], v1 = H[s1 * 4 + j];
        acc.x += v0.x * wa + v1.x * wb;
        acc.y += v0.y * wa + v1.y * wb;
        acc.z += v0.z * wa + v1.z * wb;
        acc.w += v0.w * wa + v1.w * wb;
    }
    if (e < eend) {
        int s = g_src[e];
        float wa = g_dinv[s] * din;
        float4 v = H[s * 4 + j];
        acc.x += v.x * wa; acc.y += v.y * wa; acc.z += v.z * wa; acc.w += v.w * wa;
    }
    ((float4*)g_agg)[n * 4 + j] = acc;
}

// g_h = relu(g_agg + b1), float4-wide.
__global__ void k_relu(const float* __restrict__ b1) {
    int q = blockIdx.x * blockDim.x + threadIdx.x;  // quad index
    if (q >= NN * 4) return;
    float4 b = ((const float4*)b1)[q & 3];
    float4 v = ((const float4*)g_agg)[q];
    v.x = fmaxf(v.x + b.x, 0.0f);
    v.y = fmaxf(v.y + b.y, 0.0f);
    v.z = fmaxf(v.z + b.z, 0.0f);
    v.w = fmaxf(v.w + b.w, 0.0f);
    ((float4*)g_h)[q] = v;
}

// out = g_agg @ W2 + b2. 4 rows per 256-thread block.
__global__ void k_gemm2(const float* __restrict__ W2, const float* __restrict__ b2,
                        float* __restrict__ out) {
    __shared__ float as[4 * 16];
    __shared__ float ws[16 * 64];
    int r0 = blockIdx.x * 4;
    int t = threadIdx.x;
    if (t < 64) as[t] = g_agg[r0 * HID + t];
    for (int i = t; i < 16 * 64; i += 256) ws[i] = W2[i];
    __syncthreads();
    int r = t >> 6, c = t & 63;
    float acc = b2[c];
#pragma unroll
    for (int k = 0; k < 16; k++)
        acc = fmaf(as[r * 16 + k], ws[k * 64 + c], acc);
    out[(r0 + r) * OUTC + c] = acc;
}

extern "C" void kernel_launch(void* const* d_in, const int* in_sizes, int n_in,
                              void* d_out, int out_size) {
    const float* x   = (const float*)d_in[0];
    const int*   ei  = (const int*)d_in[1];   // JAX silently downcast int64->int32
    const float* W1  = (const float*)d_in[2];
    const float* b1  = (const float*)d_in[3];
    const float* W2  = (const float*)d_in[4];
    const float* b2  = (const float*)d_in[5];
    float*       out = (float*)d_out;

    int E = in_sizes[1] / 2;
    const int* row = ei;       // sources
    const int* col = ei + E;   // targets

    k_init_deg<<<(NN + 255) / 256, 256>>>();
    k_count<<<(E + 255) / 256, 256>>>(col, E);
    k_dinv<<<(NN + 255) / 256, 256>>>();
    k_blocksum<<<NBLK, 1024>>>();
    k_bscan<<<1, 128>>>();
    k_off<<<NBLK, 1024>>>();
    k_scatter<<<(E + 255) / 256, 256>>>(row, col, E);
    k_gemm1<<<NN / 16, 256>>>(x, W1);
    k_pull<<<(NN * 4 + 255) / 256, 256>>>();
    k_relu<<<(NN * 4 + 255) / 256, 256>>>(b1);
    k_pull<<<(NN * 4 + 255) / 256, 256>>>();
    k_gemm2<<<NN / 4, 256>>>(W2, b2, out);
}

// round 12
// speedup vs baseline: 1.6744x; 1.0672x over previous
#include <cuda_runtime.h>

#define NN    100000
#define EDGES 3200000
#define INC   128
#define HID   16
#define OUTC  64
#define NBLK  ((NN + 1023) / 1024)   // 98

// Scratch (allocation-free rule: __device__ globals)
__device__ __align__(16) int    g_deg_i[NN];
__device__ __align__(16) float  g_dinv[NN];
__device__ __align__(16) int    g_off[NN + 1];
__device__ __align__(16) int    g_cur[NN];
__device__ __align__(16) float2 g_srcw[EDGES];   // {src_as_float_bits, dinv[src]}
__device__ __align__(16) int    g_bsum[NBLK];
__device__ __align__(16) int    g_boff[NBLK];
__device__ __align__(16) float  g_h[NN * HID];   // gemm1 out
__device__ __align__(16) float  g_h2[NN * HID];  // relu(agg1+b1)
__device__ __align__(16) float  g_agg[NN * HID]; // agg2

__global__ void k_init_deg() {
    int i = blockIdx.x * blockDim.x + threadIdx.x;
    if (i < NN) g_deg_i[i] = 1;  // self loop contributes 1
}

__global__ void k_count(const int* __restrict__ col, int E) {
    int i = blockIdx.x * blockDim.x + threadIdx.x;
    int e0 = i * 4;
    if (e0 + 3 < E) {
        int4 c4 = ((const int4*)col)[i];
        atomicAdd(&g_deg_i[c4.x], 1);
        atomicAdd(&g_deg_i[c4.y], 1);
        atomicAdd(&g_deg_i[c4.z], 1);
        atomicAdd(&g_deg_i[c4.w], 1);
    } else {
        for (int e = e0; e < E; e++) atomicAdd(&g_deg_i[col[e]], 1);
    }
}

__global__ void k_dinv() {
    int i = blockIdx.x * blockDim.x + threadIdx.x;
    if (i < NN) g_dinv[i] = rsqrtf((float)g_deg_i[i]);
}

// ---- 3-phase multi-block exclusive scan of (deg-1) -> g_off, g_cur ----
__global__ void k_blocksum() {
    __shared__ int sh[1024];
    int t = threadIdx.x;
    int i = blockIdx.x * 1024 + t;
    sh[t] = (i < NN) ? g_deg_i[i] - 1 : 0;
    __syncthreads();
    for (int o = 512; o > 0; o >>= 1) {
        if (t < o) sh[t] += sh[t + o];
        __syncthreads();
    }
    if (t == 0) g_bsum[blockIdx.x] = sh[0];
}

__global__ void k_bscan() {  // 1 block, 128 threads >= NBLK
    __shared__ int sh[128];
    int t = threadIdx.x;
    int v = (t < NBLK) ? g_bsum[t] : 0;
    sh[t] = v;
    __syncthreads();
    for (int o = 1; o < 128; o <<= 1) {
        int u = (t >= o) ? sh[t - o] : 0;
        __syncthreads();
        sh[t] += u;
        __syncthreads();
    }
    if (t < NBLK) g_boff[t] = sh[t] - v;  // exclusive
}

__global__ void k_off() {
    __shared__ int sh[1024];
    int t = threadIdx.x;
    int i = blockIdx.x * 1024 + t;
    int v = (i < NN) ? g_deg_i[i] - 1 : 0;
    sh[t] = v;
    __syncthreads();
    for (int o = 1; o < 1024; o <<= 1) {  // inclusive Hillis-Steele
        int u = (t >= o) ? sh[t - o] : 0;
        __syncthreads();
        sh[t] += u;
        __syncthreads();
    }
    int excl = sh[t] - v + g_boff[blockIdx.x];
    if (i < NN) {
        g_off[i] = excl;
        g_cur[i] = excl;
        if (i == NN - 1) g_off[NN] = excl + v;
    }
}

// Scatter edges into CSR, storing {src, dinv[src]} so pull never gathers dinv.
__global__ void k_scatter(const int* __restrict__ row,
                          const int* __restrict__ col, int E) {
    int e = blockIdx.x * blockDim.x + threadIdx.x;
    if (e >= E) return;
    int r = row[e];
    int p = atomicAdd(&g_cur[col[e]], 1);
    float2 v; v.x = __int_as_float(r); v.y = g_dinv[r];
    g_srcw[p] = v;
}

// h = X @ W1. Vectorized: 2x LDS.128 + 4 FFMA per 4 k's. 16 rows / 256-thread block.
__global__ void k_gemm1(const float* __restrict__ x, const float* __restrict__ W1) {
    __shared__ float4 xs[16 * 32];    // 16 rows x 32 float4 (K=128)
    __shared__ float4 wsT[16 * 33];   // 16 cols x 32 float4, stride 33 (pad)
    int r0 = blockIdx.x * 16;
    int t = threadIdx.x;
    const float4* xg = (const float4*)x;
    for (int i = t; i < 512; i += 256)
        xs[i] = xg[r0 * 32 + i];
    for (int i = t; i < 512; i += 256) {
        int c = i >> 5, k4 = i & 31;
        float4 w;
        w.x = W1[(k4 * 4 + 0) * 16 + c];
        w.y = W1[(k4 * 4 + 1) * 16 + c];
        w.z = W1[(k4 * 4 + 2) * 16 + c];
        w.w = W1[(k4 * 4 + 3) * 16 + c];
        wsT[c * 33 + k4] = w;
    }
    __syncthreads();
    int r = t >> 4, c = t & 15;
    float acc = 0.0f;
#pragma unroll
    for (int k4 = 0; k4 < 32; k4++) {
        float4 xv = xs[r * 32 + k4];
        float4 wv = wsT[c * 33 + k4];
        acc = fmaf(xv.x, wv.x, acc);
        acc = fmaf(xv.y, wv.y, acc);
        acc = fmaf(xv.z, wv.z, acc);
        acc = fmaf(xv.w, wv.w, acc);
    }
    g_h[(r0 + r) * HID + c] = acc;
}

__device__ __forceinline__ void fma4(float4& a, float4 v, float w) {
    a.x = fmaf(v.x, w, a.x); a.y = fmaf(v.y, w, a.y);
    a.z = fmaf(v.z, w, a.z); a.w = fmaf(v.w, w, a.w);
}

// Pull-mode aggregation, 4 threads/node, thread j owns cols [4j,4j+4).
// RELU=true: out = relu(acc + b1) (layer-1 epilogue fused).
template <bool RELU>
__global__ void k_pull(const float* __restrict__ src, float* __restrict__ dst,
                       const float* __restrict__ b1) {
    unsigned gid = blockIdx.x * blockDim.x + threadIdx.x;
    int n = gid >> 2;
    int j = gid & 3;
    if (n >= NN) return;
    float din = g_dinv[n];
    const float4* H = (const float4*)src;
    float4 acc = H[n * 4 + j];
    float w0 = din * din;
    acc.x *= w0; acc.y *= w0; acc.z *= w0; acc.w *= w0;
    int e = g_off[n], eend = g_off[n + 1];
    for (; e + 3 < eend; e += 4) {
        float2 p0 = g_srcw[e + 0], p1 = g_srcw[e + 1];
        float2 p2 = g_srcw[e + 2], p3 = g_srcw[e + 3];
        int s0 = __float_as_int(p0.x), s1 = __float_as_int(p1.x);
        int s2 = __float_as_int(p2.x), s3 = __float_as_int(p3.x);
        float4 v0 = H[s0 * 4 + j], v1 = H[s1 * 4 + j];
        float4 v2 = H[s2 * 4 + j], v3 = H[s3 * 4 + j];
        fma4(acc, v0, p0.y * din);
        fma4(acc, v1, p1.y * din);
        fma4(acc, v2, p2.y * din);
        fma4(acc, v3, p3.y * din);
    }
    for (; e < eend; e++) {
        float2 p = g_srcw[e];
        int s = __float_as_int(p.x);
        fma4(acc, H[s * 4 + j], p.y * din);
    }
    if (RELU) {
        float4 b = ((const float4*)b1)[j];
        acc.x = fmaxf(acc.x + b.x, 0.0f);
        acc.y = fmaxf(acc.y + b.y, 0.0f);
        acc.z = fmaxf(acc.z + b.z, 0.0f);
        acc.w = fmaxf(acc.w + b.w, 0.0f);
    }
    ((float4*)dst)[n * 4 + j] = acc;
}

// out = g_agg @ W2 + b2. 4 rows per 256-thread block.
__global__ void k_gemm2(const float* __restrict__ W2, const float* __restrict__ b2,
                        float* __restrict__ out) {
    __shared__ float as[4 * 16];
    __shared__ float ws[16 * 64];
    int r0 = blockIdx.x * 4;
    int t = threadIdx.x;
    if (t < 64) as[t] = g_agg[r0 * HID + t];
    for (int i = t; i < 16 * 64; i += 256) ws[i] = W2[i];
    __syncthreads();
    int r = t >> 6, c = t & 63;
    float acc = b2[c];
#pragma unroll
    for (int k = 0; k < 16; k++)
        acc = fmaf(as[r * 16 + k], ws[k * 64 + c], acc);
    out[(r0 + r) * OUTC + c] = acc;
}

extern "C" void kernel_launch(void* const* d_in, const int* in_sizes, int n_in,
                              void* d_out, int out_size) {
    const float* x   = (const float*)d_in[0];
    const int*   ei  = (const int*)d_in[1];   // JAX silently downcast int64->int32
    const float* W1  = (const float*)d_in[2];
    const float* b1  = (const float*)d_in[3];
    const float* W2  = (const float*)d_in[4];
    const float* b2  = (const float*)d_in[5];
    float*       out = (float*)d_out;

    int E = in_sizes[1] / 2;
    const int* row = ei;       // sources
    const int* col = ei + E;   // targets

    // device-global symbol addresses usable as kernel args only via device code;
    // instead resolve host-side once per launch (cheap, capture-safe)
    float* p_h;   cudaGetSymbolAddress((void**)&p_h,   g_h);
    float* p_h2;  cudaGetSymbolAddress((void**)&p_h2,  g_h2);
    float* p_agg; cudaGetSymbolAddress((void**)&p_agg, g_agg);

    k_init_deg<<<(NN + 255) / 256, 256>>>();
    k_count<<<(E / 4 + 255) / 256, 256>>>(col, E);
    k_dinv<<<(NN + 255) / 256, 256>>>();
    k_blocksum<<<NBLK, 1024>>>();
    k_bscan<<<1, 128>>>();
    k_off<<<NBLK, 1024>>>();
    k_scatter<<<(E + 255) / 256, 256>>>(row, col, E);
    k_gemm1<<<NN / 16, 256>>>(x, W1);
    k_pull<true><<<(NN * 4 + 255) / 256, 256>>>(p_h, p_h2, b1);
    k_pull<false><<<(NN * 4 + 255) / 256, 256>>>(p_h2, p_agg, b1);
    k_gemm2<<<NN / 4, 256>>>(W2, b2, out);
}